// round 2
// baseline (speedup 1.0000x reference)
#include <cuda_runtime.h>
#include <cuda_bf16.h>
#include <math.h>

// Problem constants (fixed by setup_inputs)
#define BB 2
#define NN 384
#define NTOK (BB*NN)            // 768
#define CS 256
#define CZ 128
#define NODE_IN 145
#define RTAB_N (2*NN-1)         // 767
#define NODE_OUT_ELEMS (NTOK*CS)            // 196608
#define EDGE_TILES (BB*NN*(NN/128))         // 2*384*3 = 2304
#define PI_F 3.14159265358979323846f

// -------- scratch (static device globals; no runtime allocation) --------
__device__ float g_nodein[NTOK * NODE_IN];
__device__ float g_U[NTOK * CZ];
__device__ float g_V[NTOK * CZ];
__device__ float g_R[RTAB_N * CZ];

// ============================================================
// Kernel 1: per-token features + U/V projections
// grid = 768 blocks, 128 threads
// ============================================================
__global__ __launch_bounds__(128) void prep_kernel(
    const float* __restrict__ atom10,    // (B,N,10,3)
    const int*   __restrict__ seq_idx,   // (B,N)
    const float* __restrict__ t,         // (B,)
    const float* __restrict__ fixed_mask,// (B,N)
    const float* __restrict__ trans,     // (B,N,3)
    const float* __restrict__ rots,      // (B,N,3,3)
    const float* __restrict__ at14,      // (B,N,14,3)
    const float* __restrict__ ew1,       // (200,128)
    const float* __restrict__ eb1)       // (128,)
{
    __shared__ float sX[NODE_IN];
    const int tok = blockIdx.x;
    const int b = tok / NN;
    const int tid = threadIdx.x;

    if (tid < 32) {
        int k = tid & 15;
        // timestep embedding: freqs = exp(k * (-ln(10000)/15)), ang = t*10000*freq
        float freq = expf((float)k * (-9.210340371976184f / 15.0f));
        float ang = t[b] * 10000.0f * freq;
        sX[tid] = (tid < 16) ? sinf(ang) : cosf(ang);
        // index embedding: ang2 = s * pi / 2056^(k/16)
        float s = (float)seq_idx[tok];
        float denom = powf(2056.0f, (float)k / 16.0f);
        float ang2 = s * PI_F / denom;
        sX[73 + tid] = (tid < 16) ? sinf(ang2) : cosf(ang2);
    }
    if (tid == 32) sX[32] = fixed_mask[tok];
    if (tid >= 33 && tid < 63) sX[tid] = atom10[tok * 30 + (tid - 33)];
    if (tid >= 63 && tid < 73) {
        int a = tid - 63;
        float x = atom10[tok * 30 + a * 3 + 0];
        float y = atom10[tok * 30 + a * 3 + 1];
        float z = atom10[tok * 30 + a * 3 + 2];
        sX[63 + a] = 1.0f / (1.0f + (x * x + y * y + z * z));
    }
    if (tid < 30) {
        int a = tid / 3, ii = tid % 3;
        const float* R  = rots + tok * 9;
        const float* tr = trans + tok * 3;
        const float* at = at14 + (tok * 14 + 4 + a) * 3;
        float v = 0.0f;
        #pragma unroll
        for (int j = 0; j < 3; j++) v += R[j * 3 + ii] * (at[j] - tr[j]);
        sX[105 + tid] = v;
    }
    __syncthreads();
    if (tid < 10) {
        float x = sX[105 + tid * 3 + 0];
        float y = sX[105 + tid * 3 + 1];
        float z = sX[105 + tid * 3 + 2];
        sX[135 + tid] = 1.0f / (1.0f + sqrtf(x * x + y * y + z * z));
    }
    __syncthreads();

    for (int i = tid; i < NODE_IN; i += 128) g_nodein[tok * NODE_IN + i] = sX[i];

    // U = A @ ew1[0:73] + eb1 ;  V = A @ ew1[73:146]
    float u = eb1[tid];
    float v = 0.0f;
    #pragma unroll 1
    for (int k = 0; k < 73; k++) {
        float a = sX[k];
        u = fmaf(a, ew1[k * CZ + tid], u);
        v = fmaf(a, ew1[(73 + k) * CZ + tid], v);
    }
    g_U[tok * CZ + tid] = u;
    g_V[tok * CZ + tid] = v;
}

// ============================================================
// Kernel 2: relative-position embedding table @ ew1[146:178]
// grid = 767 blocks, 128 threads
// ============================================================
__global__ __launch_bounds__(128) void rtab_kernel(const float* __restrict__ ew1)
{
    __shared__ float se[32];
    const int r = blockIdx.x;
    const float rel = (float)(r - (NN - 1));
    const int tid = threadIdx.x;
    if (tid < 32) {
        int k = tid & 15;
        float denom = powf(2056.0f, (float)k / 16.0f);
        float ang = rel * PI_F / denom;
        se[tid] = (tid < 16) ? sinf(ang) : cosf(ang);
    }
    __syncthreads();
    float acc = 0.0f;
    #pragma unroll
    for (int k = 0; k < 32; k++) acc = fmaf(se[k], ew1[(146 + k) * CZ + tid], acc);
    g_R[r * CZ + tid] = acc;
}

// ============================================================
// Kernel 3: node MLP (768 rows). grid = 768 blocks, 256 threads
// ============================================================
__global__ __launch_bounds__(256) void node_kernel(
    const float* __restrict__ nw1, const float* __restrict__ nb1,
    const float* __restrict__ nw2, const float* __restrict__ nb2,
    const float* __restrict__ nw3, const float* __restrict__ nb3,
    const float* __restrict__ ng,  const float* __restrict__ nbt,
    float* __restrict__ out)
{
    __shared__ float sA[CS];
    __shared__ float sBuf[CS];
    __shared__ float red[8];
    const int tok = blockIdx.x;
    const int tid = threadIdx.x;
    const int lane = tid & 31, wid = tid >> 5;

    if (tid < NODE_IN) sA[tid] = g_nodein[tok * NODE_IN + tid];
    __syncthreads();

    float h = nb1[tid];
    #pragma unroll 1
    for (int k = 0; k < NODE_IN; k++) h = fmaf(sA[k], nw1[k * CS + tid], h);
    h = fmaxf(h, 0.0f);
    sBuf[tid] = h;
    __syncthreads();

    float h2 = nb2[tid];
    #pragma unroll 1
    for (int k = 0; k < CS; k++) h2 = fmaf(sBuf[k], nw2[k * CS + tid], h2);
    h2 = fmaxf(h2, 0.0f);
    __syncthreads();
    sA[tid] = h2;
    __syncthreads();

    float h3 = nb3[tid];
    #pragma unroll 1
    for (int k = 0; k < CS; k++) h3 = fmaf(sA[k], nw3[k * CS + tid], h3);

    // LayerNorm over 256 (two-pass)
    float s = h3;
    #pragma unroll
    for (int m = 16; m >= 1; m >>= 1) s += __shfl_xor_sync(0xffffffffu, s, m);
    if (lane == 0) red[wid] = s;
    __syncthreads();
    float tot = 0.0f;
    #pragma unroll
    for (int k = 0; k < 8; k++) tot += red[k];
    float mu = tot / (float)CS;
    float d = h3 - mu;
    float s2 = d * d;
    #pragma unroll
    for (int m = 16; m >= 1; m >>= 1) s2 += __shfl_xor_sync(0xffffffffu, s2, m);
    __syncthreads();
    if (lane == 0) red[wid] = s2;
    __syncthreads();
    float tot2 = 0.0f;
    #pragma unroll
    for (int k = 0; k < 8; k++) tot2 += red[k];
    float var = tot2 / (float)CS;
    float inv = rsqrtf(var + 1e-5f);
    out[tok * CS + tid] = d * inv * ng[tid] + nbt[tid];
}

// ============================================================
// Kernel 4: edge MLP. Persistent CTAs, 1 CTA/SM.
// Tile = 128 pairs (fixed b,i; j0..j0+127) x 128 channels.
// smem: W2(64K) + W3(64K) + H(64K) + small tables
// 256 threads, 8x8 register micro-tiles per thread.
// ============================================================
#define ESM_W2   0
#define ESM_W3   16384
#define ESM_H    32768
#define ESM_B2   49152
#define ESM_B3   49280
#define ESM_G    49408
#define ESM_BT   49536
#define ESM_UI   49664
#define ESM_REL  49792
#define ESM_BIN  49920
#define ESM_FLOATS 50048

__global__ __launch_bounds__(256, 1) void edge_kernel(
    const int*   __restrict__ seq_idx,
    const float* __restrict__ trans,
    const float* __restrict__ ew1,
    const float* __restrict__ eb2,
    const float* __restrict__ ew2,
    const float* __restrict__ eb3,
    const float* __restrict__ ew3,
    const float* __restrict__ eg,
    const float* __restrict__ ebt,
    float* __restrict__ out)
{
    extern __shared__ float sm[];
    float* sW2 = sm + ESM_W2;
    float* sW3 = sm + ESM_W3;
    float* sH  = sm + ESM_H;
    float* sB2 = sm + ESM_B2;
    float* sB3 = sm + ESM_B3;
    float* sG  = sm + ESM_G;
    float* sBt = sm + ESM_BT;
    float* sUi = sm + ESM_UI;
    int*   sRel = (int*)(sm + ESM_REL);
    int*   sBin = (int*)(sm + ESM_BIN);

    const int tid = threadIdx.x;
    for (int i = tid; i < 16384; i += 256) { sW2[i] = ew2[i]; sW3[i] = ew3[i]; }
    if (tid < CZ) { sB2[tid] = eb2[tid]; sB3[tid] = eb3[tid]; sG[tid] = eg[tid]; sBt[tid] = ebt[tid]; }
    __syncthreads();

    const int tx = tid & 15;       // column group (8 cols)
    const int ty = tid >> 4;       // row group (8 rows)
    const int tx8 = tx * 8, ty8 = ty * 8;

    for (int tile = blockIdx.x; tile < EDGE_TILES; tile += gridDim.x) {
        const int bi = tile / 3;          // token index of i (b*N+i)
        const int j0 = (tile % 3) * 128;
        const int b  = bi / NN;

        __syncthreads();  // protect sH / tables from previous iteration

        if (tid < 128) {
            const int jt = b * NN + j0 + tid;
            float dx = trans[bi * 3 + 0] - trans[jt * 3 + 0];
            float dy = trans[bi * 3 + 1] - trans[jt * 3 + 1];
            float dz = trans[bi * 3 + 2] - trans[jt * 3 + 2];
            float d = sqrtf(dx * dx + dy * dy + dz * dz);
            int bin = -1;
            const float lo0 = 1e-5f;
            const float step = (20.0f - 1e-5f) / 21.0f;
            #pragma unroll
            for (int k = 0; k < 22; k++) {
                float lo = lo0 + (float)k * step;
                float hi = (k == 21) ? 1e8f : (lo0 + (float)(k + 1) * step);
                if (d > lo && d < hi) bin = k;
            }
            sBin[tid] = bin;
            int rel = seq_idx[bi] - seq_idx[jt] + (NN - 1);
            rel = max(0, min(RTAB_N - 1, rel));
            sRel[tid] = rel;
            sUi[tid] = g_U[bi * CZ + tid];
        }
        __syncthreads();

        // Build H = relu(U_i + V_j + R[rel] + W1d[bin])  (b1 folded into U)
        for (int e = tid; e < 16384; e += 256) {
            int m = e >> 7, c = e & 127;
            float v = sUi[c] + g_V[(b * NN + j0 + m) * CZ + c] + g_R[sRel[m] * CZ + c];
            int bn = sBin[m];
            if (bn >= 0) v += ew1[(178 + bn) * CZ + c];
            sH[e] = fmaxf(v, 0.0f);
        }
        __syncthreads();

        // ---- GEMM 1: C = relu(H @ W2 + b2) ----
        float acc[8][8];
        #pragma unroll
        for (int r = 0; r < 8; r++)
            #pragma unroll
            for (int c = 0; c < 8; c++) acc[r][c] = sB2[tx8 + c];

        #pragma unroll 8
        for (int k = 0; k < 128; k++) {
            float a[8];
            #pragma unroll
            for (int r = 0; r < 8; r++) a[r] = sH[(ty8 + r) * 128 + k];
            float4 b0 = *(const float4*)(sW2 + k * 128 + tx8);
            float4 b1 = *(const float4*)(sW2 + k * 128 + tx8 + 4);
            float bb[8] = { b0.x, b0.y, b0.z, b0.w, b1.x, b1.y, b1.z, b1.w };
            #pragma unroll
            for (int r = 0; r < 8; r++)
                #pragma unroll
                for (int c = 0; c < 8; c++) acc[r][c] = fmaf(a[r], bb[c], acc[r][c]);
        }
        __syncthreads();
        #pragma unroll
        for (int r = 0; r < 8; r++) {
            float4 v0, v1;
            v0.x = fmaxf(acc[r][0], 0.f); v0.y = fmaxf(acc[r][1], 0.f);
            v0.z = fmaxf(acc[r][2], 0.f); v0.w = fmaxf(acc[r][3], 0.f);
            v1.x = fmaxf(acc[r][4], 0.f); v1.y = fmaxf(acc[r][5], 0.f);
            v1.z = fmaxf(acc[r][6], 0.f); v1.w = fmaxf(acc[r][7], 0.f);
            *(float4*)(sH + (ty8 + r) * 128 + tx8)     = v0;
            *(float4*)(sH + (ty8 + r) * 128 + tx8 + 4) = v1;
        }
        __syncthreads();

        // ---- GEMM 2: C = H @ W3 + b3 ----
        #pragma unroll
        for (int r = 0; r < 8; r++)
            #pragma unroll
            for (int c = 0; c < 8; c++) acc[r][c] = sB3[tx8 + c];

        #pragma unroll 8
        for (int k = 0; k < 128; k++) {
            float a[8];
            #pragma unroll
            for (int r = 0; r < 8; r++) a[r] = sH[(ty8 + r) * 128 + k];
            float4 b0 = *(const float4*)(sW3 + k * 128 + tx8);
            float4 b1 = *(const float4*)(sW3 + k * 128 + tx8 + 4);
            float bb[8] = { b0.x, b0.y, b0.z, b0.w, b1.x, b1.y, b1.z, b1.w };
            #pragma unroll
            for (int r = 0; r < 8; r++)
                #pragma unroll
                for (int c = 0; c < 8; c++) acc[r][c] = fmaf(a[r], bb[c], acc[r][c]);
        }

        // ---- LayerNorm per row (128 vals spread over 16 lanes) + store ----
        const int itok = bi;  // b*N+i
        #pragma unroll
        for (int r = 0; r < 8; r++) {
            float s1 = 0.0f;
            #pragma unroll
            for (int c = 0; c < 8; c++) s1 += acc[r][c];
            #pragma unroll
            for (int m = 8; m >= 1; m >>= 1) s1 += __shfl_xor_sync(0xffffffffu, s1, m);
            float mu = s1 * (1.0f / 128.0f);
            float s2 = 0.0f;
            #pragma unroll
            for (int c = 0; c < 8; c++) { float dv = acc[r][c] - mu; s2 += dv * dv; }
            #pragma unroll
            for (int m = 8; m >= 1; m >>= 1) s2 += __shfl_xor_sync(0xffffffffu, s2, m);
            float inv = rsqrtf(s2 * (1.0f / 128.0f) + 1e-5f);

            int j = j0 + ty8 + r;
            size_t off = (size_t)NODE_OUT_ELEMS +
                         (((size_t)itok * NN) + j) * CZ + tx8;
            float4 o0, o1;
            o0.x = (acc[r][0] - mu) * inv * sG[tx8 + 0] + sBt[tx8 + 0];
            o0.y = (acc[r][1] - mu) * inv * sG[tx8 + 1] + sBt[tx8 + 1];
            o0.z = (acc[r][2] - mu) * inv * sG[tx8 + 2] + sBt[tx8 + 2];
            o0.w = (acc[r][3] - mu) * inv * sG[tx8 + 3] + sBt[tx8 + 3];
            o1.x = (acc[r][4] - mu) * inv * sG[tx8 + 4] + sBt[tx8 + 4];
            o1.y = (acc[r][5] - mu) * inv * sG[tx8 + 5] + sBt[tx8 + 5];
            o1.z = (acc[r][6] - mu) * inv * sG[tx8 + 6] + sBt[tx8 + 6];
            o1.w = (acc[r][7] - mu) * inv * sG[tx8 + 7] + sBt[tx8 + 7];
            *(float4*)(out + off)     = o0;
            *(float4*)(out + off + 4) = o1;
        }
    }
}

// ============================================================
extern "C" void kernel_launch(void* const* d_in, const int* in_sizes, int n_in,
                              void* d_out, int out_size)
{
    const float* atom10 = (const float*)d_in[0];
    const int*   seq    = (const int*)  d_in[1];
    const float* t      = (const float*)d_in[2];
    const float* fmask  = (const float*)d_in[3];
    // d_in[4] node_mask unused by reference
    const float* trans  = (const float*)d_in[5];
    const float* rots   = (const float*)d_in[6];
    const float* at14   = (const float*)d_in[7];
    const float* nw1 = (const float*)d_in[8];
    const float* nb1 = (const float*)d_in[9];
    const float* nw2 = (const float*)d_in[10];
    const float* nb2 = (const float*)d_in[11];
    const float* nw3 = (const float*)d_in[12];
    const float* nb3 = (const float*)d_in[13];
    const float* ng  = (const float*)d_in[14];
    const float* nbt = (const float*)d_in[15];
    const float* ew1 = (const float*)d_in[16];
    const float* eb1 = (const float*)d_in[17];
    const float* ew2 = (const float*)d_in[18];
    const float* eb2 = (const float*)d_in[19];
    const float* ew3 = (const float*)d_in[20];
    const float* eb3 = (const float*)d_in[21];
    const float* eg  = (const float*)d_in[22];
    const float* ebt = (const float*)d_in[23];
    float* out = (float*)d_out;

    static_assert(ESM_FLOATS * 4 <= 220 * 1024, "smem budget");
    cudaFuncSetAttribute(edge_kernel, cudaFuncAttributeMaxDynamicSharedMemorySize,
                         ESM_FLOATS * 4);

    prep_kernel<<<NTOK, 128>>>(atom10, seq, t, fmask, trans, rots, at14, ew1, eb1);
    rtab_kernel<<<RTAB_N, 128>>>(ew1);
    node_kernel<<<NTOK, 256>>>(nw1, nb1, nw2, nb2, nw3, nb3, ng, nbt, out);
    edge_kernel<<<148, 256, ESM_FLOATS * 4>>>(seq, trans, ew1, eb2, ew2, eb3, ew3,
                                              eg, ebt, out);
}

// round 5
// speedup vs baseline: 1.5674x; 1.5674x over previous
#include <cuda_runtime.h>
#include <cuda_fp16.h>
#include <math.h>
#include <stdint.h>

// Problem constants (fixed by setup_inputs)
#define BB 2
#define NN 384
#define NTOK (BB*NN)            // 768
#define CS 256
#define CZ 128
#define NODE_IN 145
#define RTAB_N (2*NN-1)         // 767
#define NODE_OUT_ELEMS (NTOK*CS)            // 196608
#define EDGE_TILES (BB*NN*(NN/128))         // 2304
#define PI_F 3.14159265358979323846f

// -------- scratch (static device globals; no runtime allocation) --------
__device__ float g_nodein[NTOK * NODE_IN];
__device__ float g_U[NTOK * CZ];
__device__ float g_V[NTOK * CZ];
__device__ float g_R[RTAB_N * CZ];

// ============================================================
// mma.sync helpers (standard PTX, works on bare sm_100 target)
// ============================================================
__device__ __forceinline__ uint32_t smem_to_u32(const void* p) {
    uint32_t a;
    asm("{ .reg .u64 t; cvta.to.shared.u64 t, %1; cvt.u32.u64 %0, t; }" : "=r"(a) : "l"(p));
    return a;
}
__device__ __forceinline__ void ldsm4(uint32_t& r0, uint32_t& r1, uint32_t& r2,
                                      uint32_t& r3, uint32_t addr) {
    asm volatile("ldmatrix.sync.aligned.m8n8.x4.shared.b16 {%0,%1,%2,%3}, [%4];"
                 : "=r"(r0), "=r"(r1), "=r"(r2), "=r"(r3) : "r"(addr));
}
__device__ __forceinline__ void mma16816(float* c, const uint32_t* a,
                                         uint32_t b0, uint32_t b1) {
    asm volatile("mma.sync.aligned.m16n8k16.row.col.f32.f16.f16.f32 "
                 "{%0,%1,%2,%3}, {%4,%5,%6,%7}, {%8,%9}, {%0,%1,%2,%3};"
                 : "+f"(c[0]), "+f"(c[1]), "+f"(c[2]), "+f"(c[3])
                 : "r"(a[0]), "r"(a[1]), "r"(a[2]), "r"(a[3]), "r"(b0), "r"(b1));
}
// split fp32 pair -> fp16 hi + fp16 lo (packed)
__device__ __forceinline__ void splitH2(float f0, float f1, uint32_t& hi, uint32_t& lo) {
    __half2 h = __float22half2_rn(make_float2(f0, f1));
    float2 hf = __half22float2(h);
    __half2 l = __float22half2_rn(make_float2(f0 - hf.x, f1 - hf.y));
    hi = *reinterpret_cast<uint32_t*>(&h);
    lo = *reinterpret_cast<uint32_t*>(&l);
}

// ============================================================
// Kernel 1: per-token features + U/V projections  (768 x 128)
// ============================================================
__global__ __launch_bounds__(128) void prep_kernel(
    const float* __restrict__ atom10, const int* __restrict__ seq_idx,
    const float* __restrict__ t, const float* __restrict__ fixed_mask,
    const float* __restrict__ trans, const float* __restrict__ rots,
    const float* __restrict__ at14, const float* __restrict__ ew1,
    const float* __restrict__ eb1)
{
    __shared__ float sX[NODE_IN];
    const int tok = blockIdx.x;
    const int b = tok / NN;
    const int tid = threadIdx.x;

    if (tid < 32) {
        int k = tid & 15;
        float freq = expf((float)k * (-9.210340371976184f / 15.0f));
        float ang = t[b] * 10000.0f * freq;
        sX[tid] = (tid < 16) ? sinf(ang) : cosf(ang);
        float s = (float)seq_idx[tok];
        float denom = powf(2056.0f, (float)k / 16.0f);
        float ang2 = s * PI_F / denom;
        sX[73 + tid] = (tid < 16) ? sinf(ang2) : cosf(ang2);
    }
    if (tid == 32) sX[32] = fixed_mask[tok];
    if (tid >= 33 && tid < 63) sX[tid] = atom10[tok * 30 + (tid - 33)];
    if (tid >= 63 && tid < 73) {
        int a = tid - 63;
        float x = atom10[tok * 30 + a * 3 + 0];
        float y = atom10[tok * 30 + a * 3 + 1];
        float z = atom10[tok * 30 + a * 3 + 2];
        sX[63 + a] = 1.0f / (1.0f + (x * x + y * y + z * z));
    }
    if (tid < 30) {
        int a = tid / 3, ii = tid % 3;
        const float* R  = rots + tok * 9;
        const float* tr = trans + tok * 3;
        const float* at = at14 + (tok * 14 + 4 + a) * 3;
        float v = 0.0f;
        #pragma unroll
        for (int j = 0; j < 3; j++) v += R[j * 3 + ii] * (at[j] - tr[j]);
        sX[105 + tid] = v;
    }
    __syncthreads();
    if (tid < 10) {
        float x = sX[105 + tid * 3 + 0];
        float y = sX[105 + tid * 3 + 1];
        float z = sX[105 + tid * 3 + 2];
        sX[135 + tid] = 1.0f / (1.0f + sqrtf(x * x + y * y + z * z));
    }
    __syncthreads();

    for (int i = tid; i < NODE_IN; i += 128) g_nodein[tok * NODE_IN + i] = sX[i];

    float u = eb1[tid];
    float v = 0.0f;
    #pragma unroll 1
    for (int k = 0; k < 73; k++) {
        float a = sX[k];
        u = fmaf(a, ew1[k * CZ + tid], u);
        v = fmaf(a, ew1[(73 + k) * CZ + tid], v);
    }
    g_U[tok * CZ + tid] = u;
    g_V[tok * CZ + tid] = v;
}

// ============================================================
// Kernel 2: relative-position embedding table
// ============================================================
__global__ __launch_bounds__(128) void rtab_kernel(const float* __restrict__ ew1)
{
    __shared__ float se[32];
    const int r = blockIdx.x;
    const float rel = (float)(r - (NN - 1));
    const int tid = threadIdx.x;
    if (tid < 32) {
        int k = tid & 15;
        float denom = powf(2056.0f, (float)k / 16.0f);
        float ang = rel * PI_F / denom;
        se[tid] = (tid < 16) ? sinf(ang) : cosf(ang);
    }
    __syncthreads();
    float acc = 0.0f;
    #pragma unroll
    for (int k = 0; k < 32; k++) acc = fmaf(se[k], ew1[(146 + k) * CZ + tid], acc);
    g_R[r * CZ + tid] = acc;
}

// ============================================================
// Kernel 3: node MLP, 8 tokens per block (96 blocks x 256 thr)
// ============================================================
#define TOKB 8
__global__ __launch_bounds__(256) void node_kernel(
    const float* __restrict__ nw1, const float* __restrict__ nb1,
    const float* __restrict__ nw2, const float* __restrict__ nb2,
    const float* __restrict__ nw3, const float* __restrict__ nb3,
    const float* __restrict__ ng,  const float* __restrict__ nbt,
    float* __restrict__ out)
{
    __shared__ float sA[TOKB * CS];
    __shared__ float sB[TOKB * CS];
    __shared__ float sMu[TOKB], sInv[TOKB];
    const int tok0 = blockIdx.x * TOKB;
    const int tid = threadIdx.x;
    const int lane = tid & 31, wid = tid >> 5;

    for (int idx = tid; idx < TOKB * NODE_IN; idx += 256) {
        int t = idx / NODE_IN, i = idx - t * NODE_IN;
        sA[t * CS + i] = g_nodein[(tok0 + t) * NODE_IN + i];
    }
    __syncthreads();

    float acc[TOKB];
    {
        float b = nb1[tid];
        #pragma unroll
        for (int t = 0; t < TOKB; t++) acc[t] = b;
        #pragma unroll 1
        for (int k = 0; k < NODE_IN; k++) {
            float w = nw1[k * CS + tid];
            #pragma unroll
            for (int t = 0; t < TOKB; t++) acc[t] = fmaf(sA[t * CS + k], w, acc[t]);
        }
        #pragma unroll
        for (int t = 0; t < TOKB; t++) sB[t * CS + tid] = fmaxf(acc[t], 0.0f);
    }
    __syncthreads();
    {
        float b = nb2[tid];
        #pragma unroll
        for (int t = 0; t < TOKB; t++) acc[t] = b;
        #pragma unroll 1
        for (int k = 0; k < CS; k++) {
            float w = nw2[k * CS + tid];
            #pragma unroll
            for (int t = 0; t < TOKB; t++) acc[t] = fmaf(sB[t * CS + k], w, acc[t]);
        }
    }
    __syncthreads();
    #pragma unroll
    for (int t = 0; t < TOKB; t++) sA[t * CS + tid] = fmaxf(acc[t], 0.0f);
    __syncthreads();
    {
        float b = nb3[tid];
        #pragma unroll
        for (int t = 0; t < TOKB; t++) acc[t] = b;
        #pragma unroll 1
        for (int k = 0; k < CS; k++) {
            float w = nw3[k * CS + tid];
            #pragma unroll
            for (int t = 0; t < TOKB; t++) acc[t] = fmaf(sA[t * CS + k], w, acc[t]);
        }
    }
    __syncthreads();
    #pragma unroll
    for (int t = 0; t < TOKB; t++) sB[t * CS + tid] = acc[t];
    __syncthreads();

    {
        float s1 = 0.0f, s2 = 0.0f;
        #pragma unroll
        for (int j = 0; j < 8; j++) {
            float v = sB[wid * CS + lane * 8 + j];
            s1 += v; s2 += v * v;
        }
        #pragma unroll
        for (int m = 16; m >= 1; m >>= 1) {
            s1 += __shfl_xor_sync(0xffffffffu, s1, m);
            s2 += __shfl_xor_sync(0xffffffffu, s2, m);
        }
        if (lane == 0) {
            float mu = s1 / (float)CS;
            float var = s2 / (float)CS - mu * mu;
            sMu[wid] = mu;
            sInv[wid] = rsqrtf(var + 1e-5f);
        }
    }
    __syncthreads();
    float gg = ng[tid], bb = nbt[tid];
    #pragma unroll
    for (int t = 0; t < TOKB; t++)
        out[(tok0 + t) * CS + tid] = (acc[t] - sMu[t]) * sInv[t] * gg + bb;
}

// ============================================================
// Kernel 4: edge MLP with mma.sync fp16-split GEMMs
// Persistent 148 CTAs, 256 threads (8 warps, 2x4 warp grid,
// 64x32 warp tiles), 1 CTA/SM.
// ============================================================
#define HPAD 136
#define MATB (128 * HPAD * 2)   // 34816 bytes per fp16 matrix
#define OFF_W2H 0
#define OFF_W2L (MATB)
#define OFF_W3H (2*MATB)
#define OFF_W3L (3*MATB)
#define OFF_HH  (4*MATB)
#define OFF_HL  (5*MATB)
#define OFF_B2  (6*MATB)          // 208896
#define OFF_B3  (OFF_B2+512)
#define OFF_G   (OFF_B2+1024)
#define OFF_BT  (OFF_B2+1536)
#define OFF_UI  (OFF_B2+2048)
#define OFF_REL (OFF_B2+2560)
#define OFF_BIN (OFF_B2+3072)
#define OFF_S1  (OFF_B2+3584)     // 4*128 floats = 2048B
#define OFF_S2  (OFF_S1+2048)
#define OFF_MU  (OFF_S2+2048)
#define OFF_INV (OFF_MU+512)
#define ESM_BYTES (OFF_INV+512)   // 217600

__device__ __forceinline__ void gemm_pass(float acc[4][4][4], uint32_t aBase,
                                          uint32_t bBase, uint32_t laneOff) {
    #pragma unroll
    for (int kk = 0; kk < 8; kk++) {
        uint32_t a[4][4], b[2][4];
        #pragma unroll
        for (int mt = 0; mt < 4; mt++)
            ldsm4(a[mt][0], a[mt][1], a[mt][2], a[mt][3],
                  aBase + laneOff + (uint32_t)((16 * mt * HPAD + kk * 16) * 2));
        #pragma unroll
        for (int bt = 0; bt < 2; bt++)
            ldsm4(b[bt][0], b[bt][1], b[bt][2], b[bt][3],
                  bBase + laneOff + (uint32_t)((16 * bt * HPAD + kk * 16) * 2));
        #pragma unroll
        for (int mt = 0; mt < 4; mt++)
            #pragma unroll
            for (int nt = 0; nt < 4; nt++)
                mma16816(acc[mt][nt], a[mt], b[nt >> 1][nt & 1], b[nt >> 1][2 + (nt & 1)]);
    }
}

__global__ __launch_bounds__(256, 1) void edge_kernel(
    const int*   __restrict__ seq_idx,
    const float* __restrict__ trans,
    const float* __restrict__ ew1,
    const float* __restrict__ ew2, const float* __restrict__ eb2,
    const float* __restrict__ ew3, const float* __restrict__ eb3,
    const float* __restrict__ eg,  const float* __restrict__ ebt,
    float* __restrict__ out)
{
    extern __shared__ char smem[];
    const uint32_t smem_base = smem_to_u32(smem);
    const int tid = threadIdx.x;
    const int wid = tid >> 5, lane = tid & 31;
    const int g = lane >> 2, u = lane & 3;
    const int m0 = (wid & 1) * 64;       // warp row offset
    const int n0 = (wid >> 1) * 32;      // warp col offset

    // ---- load + transpose + fp16-split weights: Wt[n][k] = W[k][n] ----
    #pragma unroll 1
    for (int mat = 0; mat < 2; mat++) {
        const float* W = mat ? ew3 : ew2;
        char* dH = smem + (mat ? OFF_W3H : OFF_W2H);
        char* dL = smem + (mat ? OFF_W3L : OFF_W2L);
        for (int e = tid; e < 2048; e += 256) {
            int n = e >> 4;
            int kg = (e & 15) << 3;
            float f[8];
            #pragma unroll
            for (int j = 0; j < 8; j++) f[j] = W[(kg + j) * CZ + n];
            uint4 hi, lo;
            splitH2(f[0], f[1], hi.x, lo.x);
            splitH2(f[2], f[3], hi.y, lo.y);
            splitH2(f[4], f[5], hi.z, lo.z);
            splitH2(f[6], f[7], hi.w, lo.w);
            uint32_t so = (uint32_t)((n * HPAD + kg) * 2);
            *(uint4*)(dH + so) = hi;
            *(uint4*)(dL + so) = lo;
        }
    }
    if (tid < CZ) {
        ((float*)(smem + OFF_B2))[tid] = eb2[tid];
        ((float*)(smem + OFF_B3))[tid] = eb3[tid];
        ((float*)(smem + OFF_G))[tid]  = eg[tid];
        ((float*)(smem + OFF_BT))[tid] = ebt[tid];
    }
    __syncthreads();

    // ldmatrix per-lane offset: row (lane&15), col-half (lane>>4)*8
    const uint32_t laneOff = (uint32_t)((((lane & 15) * HPAD) + (lane >> 4) * 8) * 2);
    const uint32_t aHH = smem_base + OFF_HH + (uint32_t)(m0 * HPAD * 2);
    const uint32_t aHL = smem_base + OFF_HL + (uint32_t)(m0 * HPAD * 2);
    const uint32_t bW2H = smem_base + OFF_W2H + (uint32_t)(n0 * HPAD * 2);
    const uint32_t bW2L = smem_base + OFF_W2L + (uint32_t)(n0 * HPAD * 2);
    const uint32_t bW3H = smem_base + OFF_W3H + (uint32_t)(n0 * HPAD * 2);
    const uint32_t bW3L = smem_base + OFF_W3L + (uint32_t)(n0 * HPAD * 2);
    const float* b2s = (const float*)(smem + OFF_B2);
    const float* b3s = (const float*)(smem + OFF_B3);

    #pragma unroll 1
    for (int tile = blockIdx.x; tile < EDGE_TILES; tile += gridDim.x) {
        const int bi = tile / 3;
        const int j0 = (tile % 3) * 128;
        const int b  = bi / NN;
        const int btok = b * NN;

        // ---- per-tile tables ----
        if (tid < 128) {
            const int jt = btok + j0 + tid;
            float dx = trans[bi * 3 + 0] - trans[jt * 3 + 0];
            float dy = trans[bi * 3 + 1] - trans[jt * 3 + 1];
            float dz = trans[bi * 3 + 2] - trans[jt * 3 + 2];
            float d = sqrtf(dx * dx + dy * dy + dz * dz);
            int bin = -1;
            const float lo0 = 1e-5f;
            const float step = (20.0f - 1e-5f) / 21.0f;
            #pragma unroll
            for (int k = 0; k < 22; k++) {
                float lo = lo0 + (float)k * step;
                float hi = (k == 21) ? 1e8f : (lo0 + (float)(k + 1) * step);
                if (d > lo && d < hi) bin = k;
            }
            ((int*)(smem + OFF_BIN))[tid] = bin;
            int rel = seq_idx[bi] - seq_idx[jt] + (NN - 1);
            rel = max(0, min(RTAB_N - 1, rel));
            ((int*)(smem + OFF_REL))[tid] = rel;
            ((float*)(smem + OFF_UI))[tid] = g_U[bi * CZ + tid];
        }
        __syncthreads();

        // ---- build H = relu(U_i + V_j + R[rel] + W1d[bin]) -> fp16 hi/lo ----
        {
            const int m = tid >> 1;
            const int ch = (tid & 1) * 64;
            const int jt = btok + j0 + m;
            const float* Vp = g_V + jt * CZ + ch;
            const int rel = ((int*)(smem + OFF_REL))[m];
            const int bin = ((int*)(smem + OFF_BIN))[m];
            const float* Rp = g_R + rel * CZ + ch;
            const float* Wp = ew1 + (178 + bin) * CZ + ch;
            const float* Up = (const float*)(smem + OFF_UI) + ch;
            #pragma unroll
            for (int gg = 0; gg < 8; gg++) {
                float4 v0 = *(const float4*)(Vp + gg * 8);
                float4 v1 = *(const float4*)(Vp + gg * 8 + 4);
                float4 r0 = *(const float4*)(Rp + gg * 8);
                float4 r1 = *(const float4*)(Rp + gg * 8 + 4);
                float4 u0 = *(const float4*)(Up + gg * 8);
                float4 u1 = *(const float4*)(Up + gg * 8 + 4);
                float f[8];
                f[0] = u0.x + v0.x + r0.x; f[1] = u0.y + v0.y + r0.y;
                f[2] = u0.z + v0.z + r0.z; f[3] = u0.w + v0.w + r0.w;
                f[4] = u1.x + v1.x + r1.x; f[5] = u1.y + v1.y + r1.y;
                f[6] = u1.z + v1.z + r1.z; f[7] = u1.w + v1.w + r1.w;
                if (bin >= 0) {
                    float4 w0 = *(const float4*)(Wp + gg * 8);
                    float4 w1 = *(const float4*)(Wp + gg * 8 + 4);
                    f[0] += w0.x; f[1] += w0.y; f[2] += w0.z; f[3] += w0.w;
                    f[4] += w1.x; f[5] += w1.y; f[6] += w1.z; f[7] += w1.w;
                }
                #pragma unroll
                for (int j = 0; j < 8; j++) f[j] = fmaxf(f[j], 0.0f);
                uint4 hi, lo;
                splitH2(f[0], f[1], hi.x, lo.x);
                splitH2(f[2], f[3], hi.y, lo.y);
                splitH2(f[4], f[5], hi.z, lo.z);
                splitH2(f[6], f[7], hi.w, lo.w);
                uint32_t so = (uint32_t)((m * HPAD + ch + gg * 8) * 2);
                *(uint4*)(smem + OFF_HH + so) = hi;
                *(uint4*)(smem + OFF_HL + so) = lo;
            }
        }
        __syncthreads();

        // ---- GEMM 1: acc = Hhi*W2hi + Hlo*W2hi + Hhi*W2lo ----
        float acc[4][4][4];
        #pragma unroll
        for (int mt = 0; mt < 4; mt++)
            #pragma unroll
            for (int nt = 0; nt < 4; nt++)
                #pragma unroll
                for (int i = 0; i < 4; i++) acc[mt][nt][i] = 0.0f;
        gemm_pass(acc, aHH, bW2H, laneOff);
        gemm_pass(acc, aHL, bW2H, laneOff);
        gemm_pass(acc, aHH, bW2L, laneOff);
        __syncthreads();   // all warps done reading H

        // ---- epilogue 1: relu(acc + b2) -> fp16 hi/lo back to H ----
        #pragma unroll
        for (int mt = 0; mt < 4; mt++) {
            int r0 = m0 + 16 * mt + g;
            #pragma unroll
            for (int nt = 0; nt < 4; nt++) {
                int c = n0 + 8 * nt + 2 * u;
                float bc0 = b2s[c], bc1 = b2s[c + 1];
                float f0 = fmaxf(acc[mt][nt][0] + bc0, 0.0f);
                float f1 = fmaxf(acc[mt][nt][1] + bc1, 0.0f);
                float f2 = fmaxf(acc[mt][nt][2] + bc0, 0.0f);
                float f3 = fmaxf(acc[mt][nt][3] + bc1, 0.0f);
                uint32_t h0, l0, h1, l1;
                splitH2(f0, f1, h0, l0);
                splitH2(f2, f3, h1, l1);
                uint32_t so0 = (uint32_t)((r0 * HPAD + c) * 2);
                uint32_t so1 = (uint32_t)(((r0 + 8) * HPAD + c) * 2);
                *(uint32_t*)(smem + OFF_HH + so0) = h0;
                *(uint32_t*)(smem + OFF_HL + so0) = l0;
                *(uint32_t*)(smem + OFF_HH + so1) = h1;
                *(uint32_t*)(smem + OFF_HL + so1) = l1;
            }
        }
        __syncthreads();

        // ---- GEMM 2: acc = Hhi*W3hi + Hlo*W3hi + Hhi*W3lo ----
        #pragma unroll
        for (int mt = 0; mt < 4; mt++)
            #pragma unroll
            for (int nt = 0; nt < 4; nt++)
                #pragma unroll
                for (int i = 0; i < 4; i++) acc[mt][nt][i] = 0.0f;
        gemm_pass(acc, aHH, bW3H, laneOff);
        gemm_pass(acc, aHL, bW3H, laneOff);
        gemm_pass(acc, aHH, bW3L, laneOff);

        // ---- epilogue 2: +b3, LayerNorm over 128 cols, scale, store ----
        // add bias in place
        #pragma unroll
        for (int mt = 0; mt < 4; mt++)
            #pragma unroll
            for (int nt = 0; nt < 4; nt++) {
                int c = n0 + 8 * nt + 2 * u;
                acc[mt][nt][0] += b3s[c];
                acc[mt][nt][1] += b3s[c + 1];
                acc[mt][nt][2] += b3s[c];
                acc[mt][nt][3] += b3s[c + 1];
            }
        // per-row partial sums over this warp's 32 cols
        {
            float* S1 = (float*)(smem + OFF_S1);
            float* S2 = (float*)(smem + OFF_S2);
            const int wq = (wid >> 1);  // warp_n 0..3
            #pragma unroll
            for (int mt = 0; mt < 4; mt++) {
                float s1a = 0.f, s2a = 0.f, s1b = 0.f, s2b = 0.f;
                #pragma unroll
                for (int nt = 0; nt < 4; nt++) {
                    float f0 = acc[mt][nt][0], f1 = acc[mt][nt][1];
                    float f2 = acc[mt][nt][2], f3 = acc[mt][nt][3];
                    s1a += f0 + f1; s2a += f0 * f0 + f1 * f1;
                    s1b += f2 + f3; s2b += f2 * f2 + f3 * f3;
                }
                #pragma unroll
                for (int m = 1; m <= 2; m <<= 1) {
                    s1a += __shfl_xor_sync(0xffffffffu, s1a, m);
                    s2a += __shfl_xor_sync(0xffffffffu, s2a, m);
                    s1b += __shfl_xor_sync(0xffffffffu, s1b, m);
                    s2b += __shfl_xor_sync(0xffffffffu, s2b, m);
                }
                if (u == 0) {
                    int r0 = m0 + 16 * mt + g;
                    S1[wq * 128 + r0] = s1a; S2[wq * 128 + r0] = s2a;
                    S1[wq * 128 + r0 + 8] = s1b; S2[wq * 128 + r0 + 8] = s2b;
                }
            }
        }
        __syncthreads();
        if (tid < 128) {
            const float* S1 = (const float*)(smem + OFF_S1);
            const float* S2 = (const float*)(smem + OFF_S2);
            float ts = S1[tid] + S1[128 + tid] + S1[256 + tid] + S1[384 + tid];
            float tq = S2[tid] + S2[128 + tid] + S2[256 + tid] + S2[384 + tid];
            float mu = ts * (1.0f / 128.0f);
            float var = tq * (1.0f / 128.0f) - mu * mu;
            ((float*)(smem + OFF_MU))[tid]  = mu;
            ((float*)(smem + OFF_INV))[tid] = rsqrtf(var + 1e-5f);
        }
        __syncthreads();
        {
            const float* MU  = (const float*)(smem + OFF_MU);
            const float* INV = (const float*)(smem + OFF_INV);
            const float* G   = (const float*)(smem + OFF_G);
            const float* BT  = (const float*)(smem + OFF_BT);
            #pragma unroll
            for (int mt = 0; mt < 4; mt++) {
                int r0 = m0 + 16 * mt + g;
                float mu0 = MU[r0], iv0 = INV[r0];
                float mu1 = MU[r0 + 8], iv1 = INV[r0 + 8];
                float* base0 = out + (size_t)NODE_OUT_ELEMS +
                               ((size_t)bi * NN + (j0 + r0)) * CZ;
                float* base1 = out + (size_t)NODE_OUT_ELEMS +
                               ((size_t)bi * NN + (j0 + r0 + 8)) * CZ;
                #pragma unroll
                for (int nt = 0; nt < 4; nt++) {
                    int c = n0 + 8 * nt + 2 * u;
                    float g0 = G[c], g1 = G[c + 1], t0 = BT[c], t1 = BT[c + 1];
                    float2 o0, o1;
                    o0.x = (acc[mt][nt][0] - mu0) * iv0 * g0 + t0;
                    o0.y = (acc[mt][nt][1] - mu0) * iv0 * g1 + t1;
                    o1.x = (acc[mt][nt][2] - mu1) * iv1 * g0 + t0;
                    o1.y = (acc[mt][nt][3] - mu1) * iv1 * g1 + t1;
                    *(float2*)(base0 + c) = o0;
                    *(float2*)(base1 + c) = o1;
                }
            }
        }
        __syncthreads();
    }
}

// ============================================================
extern "C" void kernel_launch(void* const* d_in, const int* in_sizes, int n_in,
                              void* d_out, int out_size)
{
    const float* atom10 = (const float*)d_in[0];
    const int*   seq    = (const int*)  d_in[1];
    const float* t      = (const float*)d_in[2];
    const float* fmask  = (const float*)d_in[3];
    const float* trans  = (const float*)d_in[5];
    const float* rots   = (const float*)d_in[6];
    const float* at14   = (const float*)d_in[7];
    const float* nw1 = (const float*)d_in[8];
    const float* nb1 = (const float*)d_in[9];
    const float* nw2 = (const float*)d_in[10];
    const float* nb2 = (const float*)d_in[11];
    const float* nw3 = (const float*)d_in[12];
    const float* nb3 = (const float*)d_in[13];
    const float* ng  = (const float*)d_in[14];
    const float* nbt = (const float*)d_in[15];
    const float* ew1 = (const float*)d_in[16];
    const float* eb1 = (const float*)d_in[17];
    const float* ew2 = (const float*)d_in[18];
    const float* eb2 = (const float*)d_in[19];
    const float* ew3 = (const float*)d_in[20];
    const float* eb3 = (const float*)d_in[21];
    const float* eg  = (const float*)d_in[22];
    const float* ebt = (const float*)d_in[23];
    float* out = (float*)d_out;

    cudaFuncSetAttribute(edge_kernel, cudaFuncAttributeMaxDynamicSharedMemorySize,
                         ESM_BYTES);

    prep_kernel<<<NTOK, 128>>>(atom10, seq, t, fmask, trans, rots, at14, ew1, eb1);
    rtab_kernel<<<RTAB_N, 128>>>(ew1);
    node_kernel<<<NTOK / TOKB, 256>>>(nw1, nb1, nw2, nb2, nw3, nb3, ng, nbt, out);
    edge_kernel<<<148, 256, ESM_BYTES>>>(seq, trans, ew1, ew2, eb2, ew3, eb3,
                                         eg, ebt, out);
}